// round 3
// baseline (speedup 1.0000x reference)
#include <cuda_runtime.h>
#include <cstdint>

// Problem constants
#define RR 4
#define ND 81
#define NB 4
#define NC 128
#define NH 96
#define NW 160

// Tiling
#define TX 32
#define YB 8
#define PX 8
#define XG 4                  // TX/PX
#define NDY 9
#define NTHREADS 288          // XG*NDY*YB = 9 warps
#define CCHUNK 8
#define NCHUNK 16
#define TGT_W 44              // (TX + 2*RR)=40, padded to 44 (bank-conflict-free)
#define TGT_H (YB + 2*RR)     // 16
#define TGT_TILE (CCHUNK*TGT_H*TGT_W)   // 5632 floats
#define SRC_TILE (CCHUNK*YB*TX)         // 2048 floats
#define BUF_FLOATS (TGT_TILE + SRC_TILE) // 7680
#define BUF_BYTES (BUF_FLOATS*4)         // 30720
#define NQUADS (BUF_FLOATS/4)            // 1920
#define MAXSLOTS 7
#define CBYTES (CCHUNK*NH*NW*4)          // bytes per channel-chunk step

__device__ __forceinline__ int disp_index(int dyv, int dxv) {
    int ay = dyv < 0 ? -dyv : dyv;
    int ax = dxv < 0 ? -dxv : dxv;
    if ((ay | ax) == 0) return 0;
    if (ax == 0) return 1 + (ay - 1) * 20 + (dyv < 0 ? 0 : 1);
    if (ay == 0) return 1 + (ax - 1) * 20 + (dxv < 0 ? 2 : 3);
    int base = 1 + (ay - 1) * 20 + 4 + (ax - 1) * 4;
    if (dyv < 0 && dxv < 0) return base + 0;
    if (dyv > 0 && dxv > 0) return base + 1;
    if (dyv < 0 && dxv > 0) return base + 2;
    return base + 3;
}

__device__ __forceinline__ void cp_async16(uint32_t saddr, const void* gaddr, int sz) {
    asm volatile("cp.async.cg.shared.global [%0], [%1], 16, %2;\n"
                 :: "r"(saddr), "l"(gaddr), "r"(sz));
}
__device__ __forceinline__ void cp_commit() {
    asm volatile("cp.async.commit_group;\n" ::: "memory");
}
__device__ __forceinline__ unsigned long long pk2(float lo, float hi) {
    unsigned long long r;
    asm("mov.b64 %0, {%1, %2};" : "=l"(r) : "f"(lo), "f"(hi));
    return r;
}
__device__ __forceinline__ void upk2(unsigned long long v, float& lo, float& hi) {
    asm("mov.b64 {%0, %1}, %2;" : "=f"(lo), "=f"(hi) : "l"(v));
}
__device__ __forceinline__ void fma2(unsigned long long& d,
                                     unsigned long long a, unsigned long long b) {
    asm("fma.rn.f32x2 %0, %1, %2, %0;" : "+l"(d) : "l"(a), "l"(b));
}

__global__ __launch_bounds__(NTHREADS, 2)
void costvol_kernel(const float* __restrict__ src,
                    const float* __restrict__ tgt,
                    float* __restrict__ out) {
    __shared__ __align__(16) float sm[2][BUF_FLOATS];

    const int tid = threadIdx.x;
    const int x0 = blockIdx.x * TX;
    const int y0 = blockIdx.y * YB;
    const int b  = blockIdx.z;

    const char* srcB = (const char*)(src + (size_t)b * NC * NH * NW);
    const char* tgtB = (const char*)(tgt + (size_t)b * NC * NH * NW);

    // ---- staging slots: slot k handles quad idx = tid + k*NTHREADS,
    //      smem byte offset = idx*16 (linear layout). Only a 32-bit global
    //      byte offset + 2 flag bits per slot are kept in registers. ----
    uint32_t goff[MAXSLOTS];
    uint32_t flags = 0;   // bit k: slot is tgt; bit k+8: in-bounds
#pragma unroll
    for (int k = 0; k < MAXSLOTS; k++) {
        int idx = tid + k * NTHREADS;
        goff[k] = 0;
        if (idx < NQUADS) {
            if (idx < TGT_TILE / 4) {
                int cc  = idx / (TGT_H * TGT_W / 4);      // /176
                int rem = idx % (TGT_H * TGT_W / 4);
                int row = rem / (TGT_W / 4);              // /11
                int xq  = rem % (TGT_W / 4);
                int gy = y0 + row - RR;
                int gx = x0 + xq * 4 - RR;
                bool ok = ((unsigned)gy < NH) && ((unsigned)gx < NW);
                if (ok) goff[k] = (uint32_t)(((cc * NH + gy) * NW + gx) * 4);
                flags |= 1u << k;
                if (ok) flags |= 1u << (k + 8);
            } else {
                int q   = idx - TGT_TILE / 4;
                int cc  = q / (YB * TX / 4);              // /64
                int rem = q % (YB * TX / 4);
                int ry  = rem / (TX / 4);
                int xq  = rem % (TX / 4);
                goff[k] = (uint32_t)(((cc * NH + y0 + ry) * NW + x0 + xq * 4) * 4);
                flags |= 1u << (k + 8);
            }
        }
    }

    const uint32_t smem_base = (uint32_t)__cvta_generic_to_shared(&sm[0][0]);

    // ---- compute role ----
    const int xg   = tid & (XG - 1);
    const int dyi  = (tid >> 2) % NDY;
    const int yr   = tid / (XG * NDY);
    const int dyv  = dyi - RR;
    const int trow = yr + dyi;            // 0..15

    const int t_off = trow * TGT_W + xg * PX;              // floats
    const int s_off = TGT_TILE + yr * TX + xg * PX;        // floats

    unsigned long long acc[NDY][4];
#pragma unroll
    for (int i = 0; i < NDY; i++)
#pragma unroll
        for (int j = 0; j < 4; j++) acc[i][j] = 0ull;

    // ---- prologue: stage chunk 0 ----
#pragma unroll
    for (int k = 0; k < MAXSLOTS; k++) {
        if (k < MAXSLOTS - 1 || tid < NQUADS - (MAXSLOTS - 1) * NTHREADS) {
            const char* base = (flags >> k & 1) ? tgtB : srcB;
            int sz = (flags >> (k + 8) & 1) ? 16 : 0;
            cp_async16(smem_base + (uint32_t)(tid + k * NTHREADS) * 16,
                       base + goff[k], sz);
            goff[k] += CBYTES;
        }
    }
    cp_commit();

#pragma unroll 1
    for (int ch = 0; ch < NCHUNK; ch++) {
        if (ch + 1 < NCHUNK) {
            const uint32_t bofs = ((ch + 1) & 1) * BUF_BYTES;
#pragma unroll
            for (int k = 0; k < MAXSLOTS; k++) {
                if (k < MAXSLOTS - 1 || tid < NQUADS - (MAXSLOTS - 1) * NTHREADS) {
                    const char* base = (flags >> k & 1) ? tgtB : srcB;
                    int sz = (flags >> (k + 8) & 1) ? 16 : 0;
                    cp_async16(smem_base + bofs + (uint32_t)(tid + k * NTHREADS) * 16,
                               base + goff[k], sz);
                    goff[k] += CBYTES;
                }
            }
            cp_commit();
            asm volatile("cp.async.wait_group 1;\n" ::: "memory");
        } else {
            asm volatile("cp.async.wait_group 0;\n" ::: "memory");
        }
        __syncthreads();

        const float* bp = &sm[ch & 1][0];
        const float* tb = bp + t_off;
        const float* sb = bp + s_off;
#pragma unroll
        for (int cc = 0; cc < CCHUNK; cc++) {
            const float4 s0 = *(const float4*)(sb + cc * (YB * TX));
            const float4 s1 = *(const float4*)(sb + cc * (YB * TX) + 4);
            const float4* tq = (const float4*)(tb + cc * (TGT_H * TGT_W));
            const float4 t0 = tq[0], t1 = tq[1], t2 = tq[2], t3 = tq[3];

            float t[16] = {t0.x, t0.y, t0.z, t0.w, t1.x, t1.y, t1.z, t1.w,
                           t2.x, t2.y, t2.z, t2.w, t3.x, t3.y, t3.z, t3.w};

            unsigned long long sp[4] = {pk2(s0.x, s0.y), pk2(s0.z, s0.w),
                                        pk2(s1.x, s1.y), pk2(s1.z, s1.w)};
            unsigned long long ap[8], sh[7];
#pragma unroll
            for (int i = 0; i < 8; i++) ap[i] = pk2(t[2 * i], t[2 * i + 1]);
#pragma unroll
            for (int i = 0; i < 7; i++) sh[i] = pk2(t[2 * i + 1], t[2 * i + 2]);

#pragma unroll
            for (int e = 0; e < 5; e++)         // dx = 0,2,4,6,8
#pragma unroll
                for (int j = 0; j < 4; j++)
                    fma2(acc[2 * e][j], sp[j], ap[e + j]);
#pragma unroll
            for (int o = 0; o < 4; o++)         // dx = 1,3,5,7
#pragma unroll
                for (int j = 0; j < 4; j++)
                    fma2(acc[2 * o + 1][j], sp[j], sh[o + j]);
        }
        __syncthreads();
    }

    // ---- epilogue ----
    const float inv = 1.0f / 81.0f;
    const int y = y0 + yr;
#pragma unroll
    for (int dx = 0; dx < NDY; dx++) {
        int d = disp_index(dyv, dx - RR);
        float* o = out + ((((size_t)b * ND + d) * NH) + y) * NW + x0 + xg * PX;
        float a[8];
#pragma unroll
        for (int j = 0; j < 4; j++) upk2(acc[dx][j], a[2 * j], a[2 * j + 1]);
        float4 v0 = make_float4(a[0] * inv, a[1] * inv, a[2] * inv, a[3] * inv);
        float4 v1 = make_float4(a[4] * inv, a[5] * inv, a[6] * inv, a[7] * inv);
        *(float4*)o = v0;
        *((float4*)o + 1) = v1;
    }
}

extern "C" void kernel_launch(void* const* d_in, const int* in_sizes, int n_in,
                              void* d_out, int out_size) {
    const float* src = (const float*)d_in[0];
    const float* tgt = (const float*)d_in[1];
    float* out = (float*)d_out;

    dim3 grid(NW / TX, NH / YB, NB);   // (5, 12, 4) = 240 blocks
    dim3 block(NTHREADS);              // 288 threads = 9 warps
    costvol_kernel<<<grid, block>>>(src, tgt, out);
}

// round 4
// speedup vs baseline: 1.3829x; 1.3829x over previous
#include <cuda_runtime.h>
#include <cstdint>

// Problem constants
#define RR 4
#define ND 81
#define NB 4
#define NC 128
#define NH 96
#define NW 160

// Tiling (R2 winner geometry)
#define TX 32
#define YB 4
#define PX 4
#define XG 8                 // TX/PX
#define NDY 9
#define NTHREADS 288         // 9 warps
#define CCHUNK 8
#define NCHUNK 16            // NC/CCHUNK
#define TGT_W (TX + 2*RR)    // 40
#define TGT_H (YB + 2*RR)    // 12
#define TGT_TILE (CCHUNK*TGT_H*TGT_W)   // 3840 floats
#define SRC_TILE (CCHUNK*YB*TX)         // 1024 floats
#define BUF_FLOATS (TGT_TILE + SRC_TILE) // 4864
#define BUF_BYTES (BUF_FLOATS*4)         // 19456
#define NQUADS (BUF_FLOATS/4)            // 1216
#define MAXSLOTS 5
#define CBYTES (CCHUNK*NH*NW*4)          // global bytes per chunk step

__device__ __forceinline__ int disp_index(int dyv, int dxv) {
    int ay = dyv < 0 ? -dyv : dyv;
    int ax = dxv < 0 ? -dxv : dxv;
    if ((ay | ax) == 0) return 0;
    if (ax == 0) return 1 + (ay - 1) * 20 + (dyv < 0 ? 0 : 1);
    if (ay == 0) return 1 + (ax - 1) * 20 + (dxv < 0 ? 2 : 3);
    int base = 1 + (ay - 1) * 20 + 4 + (ax - 1) * 4;
    if (dyv < 0 && dxv < 0) return base + 0;
    if (dyv > 0 && dxv > 0) return base + 1;
    if (dyv < 0 && dxv > 0) return base + 2;
    return base + 3;
}

__device__ __forceinline__ void cp_async16(uint32_t saddr, const void* gaddr, int sz) {
    asm volatile("cp.async.cg.shared.global [%0], [%1], 16, %2;\n"
                 :: "r"(saddr), "l"(gaddr), "r"(sz));
}
__device__ __forceinline__ void cp_commit() {
    asm volatile("cp.async.commit_group;\n" ::: "memory");
}

__global__ __launch_bounds__(NTHREADS, 3)
void costvol_kernel(const float* __restrict__ src,
                    const float* __restrict__ tgt,
                    float* __restrict__ out) {
    __shared__ __align__(16) float sm[3][BUF_FLOATS];   // triple buffer

    const int tid = threadIdx.x;
    const int x0 = blockIdx.x * TX;
    const int y0 = blockIdx.y * YB;
    const int b  = blockIdx.z;

    const char* srcB = (const char*)(src + (size_t)b * NC * NH * NW);
    const char* tgtB = (const char*)(tgt + (size_t)b * NC * NH * NW);

    // ---- compressed staging state: slot k covers quad idx = tid + k*288,
    //      smem offset is linear (idx*16 within buffer); keep only a u32
    //      global byte offset per slot + flag bits. ----
    uint32_t goff[MAXSLOTS];
    uint32_t flags = 0;   // bit k: slot targets tgt; bit k+8: in-bounds
#pragma unroll
    for (int k = 0; k < MAXSLOTS; k++) {
        int idx = tid + k * NTHREADS;
        goff[k] = 0;
        if (idx < NQUADS) {
            if (idx < TGT_TILE / 4) {
                int cc  = idx / (TGT_H * TGT_W / 4);     // /120
                int rem = idx % (TGT_H * TGT_W / 4);
                int row = rem / (TGT_W / 4);             // /10
                int xq  = rem % (TGT_W / 4);
                int gy = y0 + row - RR;
                int gx = x0 + xq * 4 - RR;
                bool ok = ((unsigned)gy < NH) && ((unsigned)gx < NW);
                if (ok) goff[k] = (uint32_t)(((cc * NH + gy) * NW + gx) * 4);
                flags |= 1u << k;
                if (ok) flags |= 1u << (k + 8);
            } else {
                int q   = idx - TGT_TILE / 4;
                int cc  = q / (YB * TX / 4);             // /32
                int rem = q % (YB * TX / 4);
                int ry  = rem / (TX / 4);
                int xq  = rem % (TX / 4);
                goff[k] = (uint32_t)(((cc * NH + y0 + ry) * NW + x0 + xq * 4) * 4);
                flags |= 1u << (k + 8);
            }
        }
    }

    const uint32_t smem_base = (uint32_t)__cvta_generic_to_shared(&sm[0][0]);

    // ---- compute role ----
    const int xg   = tid & (XG - 1);
    const int dyi  = (tid >> 3) % NDY;
    const int yr   = tid / (XG * NDY);
    const int dyv  = dyi - RR;
    const int trow = yr + dyi;                       // 0..11
    const int t_off = trow * TGT_W + xg * PX;        // floats
    const int s_off = TGT_TILE + yr * TX + xg * PX;  // floats

    float acc[NDY][PX];
#pragma unroll
    for (int i = 0; i < NDY; i++)
#pragma unroll
        for (int p = 0; p < PX; p++) acc[i][p] = 0.0f;

    // ---- stage helper (macro-ish lambda): issue one chunk into buffer bi ----
    auto stage = [&](int bi) {
        const uint32_t bofs = (uint32_t)bi * BUF_BYTES;
#pragma unroll
        for (int k = 0; k < MAXSLOTS; k++) {
            if (k < MAXSLOTS - 1 || tid < NQUADS - (MAXSLOTS - 1) * NTHREADS) {
                const char* base = (flags >> k & 1) ? tgtB : srcB;
                int sz = (flags >> (k + 8) & 1) ? 16 : 0;
                cp_async16(smem_base + bofs + (uint32_t)(tid + k * NTHREADS) * 16,
                           base + goff[k], sz);
                goff[k] += CBYTES;
            }
        }
        cp_commit();
    };

    // ---- prologue: prefetch chunks 0 and 1 ----
    stage(0);
    stage(1);

#pragma unroll 1
    for (int ch = 0; ch < NCHUNK; ch++) {
        if (ch + 2 < NCHUNK)
            asm volatile("cp.async.wait_group 1;\n" ::: "memory");
        else
            asm volatile("cp.async.wait_group 0;\n" ::: "memory");
        __syncthreads();   // chunk ch resident in buf ch%3 for all threads

        const float* bp = &sm[0][0] + (ch % 3) * BUF_FLOATS;
        const float* tb = bp + t_off;
        const float* sb = bp + s_off;
#pragma unroll
        for (int cc = 0; cc < CCHUNK; cc++) {
            float4 s4 = *(const float4*)(sb + cc * (YB * TX));
            const float4* tq = (const float4*)(tb + cc * (TGT_H * TGT_W));
            float4 t0 = tq[0], t1 = tq[1], t2 = tq[2];
            float s[PX] = {s4.x, s4.y, s4.z, s4.w};
            float t[12] = {t0.x, t0.y, t0.z, t0.w,
                           t1.x, t1.y, t1.z, t1.w,
                           t2.x, t2.y, t2.z, t2.w};
#pragma unroll
            for (int dx = 0; dx < NDY; dx++)
#pragma unroll
                for (int p = 0; p < PX; p++)
                    acc[dx][p] = fmaf(s[p], t[dx + p], acc[dx][p]);
        }

        // prefetch chunk ch+2 into buf (ch+2)%3 == (ch-1)%3: safe, everyone
        // passed this iteration's barrier, so chunk ch-1 is fully consumed.
        if (ch + 2 < NCHUNK)
            stage((ch + 2) % 3);
    }

    // ---- epilogue: scale + scatter ----
    const float inv = 1.0f / 81.0f;
    const int y = y0 + yr;
#pragma unroll
    for (int dx = 0; dx < NDY; dx++) {
        int d = disp_index(dyv, dx - RR);
        float* o = out + ((((size_t)b * ND + d) * NH) + y) * NW + x0 + xg * PX;
        float4 v = make_float4(acc[dx][0] * inv, acc[dx][1] * inv,
                               acc[dx][2] * inv, acc[dx][3] * inv);
        *(float4*)o = v;
    }
}

extern "C" void kernel_launch(void* const* d_in, const int* in_sizes, int n_in,
                              void* d_out, int out_size) {
    const float* src = (const float*)d_in[0];
    const float* tgt = (const float*)d_in[1];
    float* out = (float*)d_out;

    dim3 grid(NW / TX, NH / YB, NB);   // (5, 24, 4) = 480 blocks
    dim3 block(NTHREADS);              // 288 threads = 9 warps
    costvol_kernel<<<grid, block>>>(src, tgt, out);
}